// round 17
// baseline (speedup 1.0000x reference)
#include <cuda_runtime.h>
#include <cuda_fp16.h>
#include <stdint.h>

#define N_NODES 50000
#define N_EDGES 800000
#define D 96
#define DC 24              // D / 4 (float4 chunks per row)
#define XS_STRIDE 25       // padded row stride in float4
#define GEMM_ROWS 128      // rows per block
#define GEMM_THREADS 192   // 12 col-groups x 16 row-groups
#define GEMM_SMEM ((D * DC + GEMM_ROWS * XS_STRIDE) * 16)
#define SCAN_THREADS 1024

// Scratch (device globals; no allocation allowed)
__device__ int    g_is64;
__device__ float  g_deg[N_NODES];
__device__ int    g_cnt[N_NODES];
__device__ int    g_cursor[N_NODES];
__device__ int    g_off[N_NODES + 1];
__device__ __half g_h[(size_t)N_NODES * D];    // h * dinv[row], fp16
__device__ int2   g_srt[N_EDGES];              // CSR by col: {row, bits(ew*dinv[col])}

// packed f32x2 helpers (sm_103a FFMA2 — PTX only)
__device__ __forceinline__ unsigned long long pack2(float x, float y) {
    unsigned long long p;
    asm("mov.b64 %0, {%1, %2};" : "=l"(p) : "f"(x), "f"(y));
    return p;
}
__device__ __forceinline__ void fma2(unsigned long long& acc,
                                     unsigned long long a,
                                     unsigned long long b) {
    asm("fma.rn.f32x2 %0, %1, %2, %0;" : "+l"(acc) : "l"(a), "l"(b));
}
__device__ __forceinline__ void unpack2(unsigned long long p, float& x, float& y) {
    asm("mov.b64 {%0, %1}, %2;" : "=f"(x), "=f"(y) : "l"(p));
}

// ---------------------------------------------------------------------------
// 1. init: deg = 1 (self loop), cnt = cursor = 0; thread 0 detects idx dtype.
// ---------------------------------------------------------------------------
__global__ void init_kernel(const int* __restrict__ ei32) {
    int i = blockIdx.x * blockDim.x + threadIdx.x;
    if (i < N_NODES) {
        g_deg[i] = 1.0f;
        g_cnt[i] = 0;
        g_cursor[i] = 0;
    }
    if (i == 0) {
        int looks64 = 1, any_nonzero = 0;
        #pragma unroll
        for (int k = 0; k < 64; k++) {
            if (ei32[2 * k + 1] != 0) looks64 = 0;
            if (ei32[2 * k] != 0) any_nonzero = 1;
        }
        g_is64 = (looks64 && any_nonzero) ? 1 : 0;
    }
}

// ---------------------------------------------------------------------------
// 2. deg[col] += ew ; cnt[col] += 1
// ---------------------------------------------------------------------------
__global__ void accum_deg_kernel(const void* __restrict__ ei,
                                 const float* __restrict__ ew) {
    int e = blockIdx.x * blockDim.x + threadIdx.x;
    if (e < N_EDGES) {
        int col = g_is64 ? (int)((const long long*)ei)[(size_t)N_EDGES + e]
                         : ((const int*)ei)[(size_t)N_EDGES + e];
        atomicAdd(&g_deg[col], ew[e]);
        atomicAdd(&g_cnt[col], 1);
    }
}

// ---------------------------------------------------------------------------
// 3. single-block exclusive scan: g_cnt -> g_off
// ---------------------------------------------------------------------------
__global__ __launch_bounds__(SCAN_THREADS)
void scan_kernel() {
    __shared__ int part[SCAN_THREADS];
    const int CH = (N_NODES + SCAN_THREADS - 1) / SCAN_THREADS;  // 49
    int t = threadIdx.x;
    int beg = t * CH;
    int end = min(beg + CH, N_NODES);

    int s = 0;
    for (int i = beg; i < end; i++) s += g_cnt[i];
    part[t] = s;
    __syncthreads();

    #pragma unroll
    for (int ofs = 1; ofs < SCAN_THREADS; ofs <<= 1) {
        int v = (t >= ofs) ? part[t - ofs] : 0;
        __syncthreads();
        part[t] += v;
        __syncthreads();
    }

    int run = part[t] - s;
    for (int i = beg; i < end; i++) {
        g_off[i] = run;
        run += g_cnt[i];
    }
    if (t == SCAN_THREADS - 1) g_off[N_NODES] = part[SCAN_THREADS - 1];
}

// ---------------------------------------------------------------------------
// 4. place: counting-sort edges by col; store {row, ew * rsqrt(deg[col])}
// ---------------------------------------------------------------------------
__global__ void place_kernel(const void* __restrict__ ei,
                             const float* __restrict__ ew) {
    int e = blockIdx.x * blockDim.x + threadIdx.x;
    if (e < N_EDGES) {
        int is64 = g_is64;
        int row, col;
        if (is64) {
            row = (int)((const long long*)ei)[e];
            col = (int)((const long long*)ei)[(size_t)N_EDGES + e];
        } else {
            row = ((const int*)ei)[e];
            col = ((const int*)ei)[(size_t)N_EDGES + e];
        }
        float nrm = ew[e] * rsqrtf(g_deg[col]);
        int pos = g_off[col] + atomicAdd(&g_cursor[col], 1);
        g_srt[pos] = make_int2(row, __float_as_int(nrm));
    }
}

// ---------------------------------------------------------------------------
// 5. GEMM:  h' = (x @ W) * dinv[row]  -> g_h (fp16).  (R14 config, no out)
// ---------------------------------------------------------------------------
__global__ __launch_bounds__(GEMM_THREADS)
void gemm_kernel(const float* __restrict__ x, const float* __restrict__ W) {
    extern __shared__ float smem[];
    float4* Ws4 = (float4*)smem;
    float4* Xs4 = (float4*)(smem + D * D);

    int tid = threadIdx.x;
    int row0 = blockIdx.x * GEMM_ROWS;

    const float4* W4 = (const float4*)W;
    #pragma unroll
    for (int i = tid; i < D * DC; i += GEMM_THREADS) Ws4[i] = W4[i];

    const float4* X4 = (const float4*)x;
    #pragma unroll
    for (int i = tid; i < GEMM_ROWS * DC; i += GEMM_THREADS) {
        int r = i / DC;
        int c = i - r * DC;
        int gr = row0 + r;
        Xs4[r * XS_STRIDE + c] = (gr < N_NODES) ? X4[(size_t)gr * DC + c]
                                                : make_float4(0.f, 0.f, 0.f, 0.f);
    }
    __syncthreads();

    int tx = tid % 12;
    int ty = tid / 12;
    int rbase = ty * 8;
    int c0 = 2 * tx, c1 = 2 * tx + 1;

    unsigned long long acc[8][4];
    #pragma unroll
    for (int r = 0; r < 8; r++)
        #pragma unroll
        for (int q = 0; q < 4; q++) acc[r][q] = 0ull;

    #pragma unroll 2
    for (int kc = 0; kc < DC; kc++) {
        float4 xv[8];
        #pragma unroll
        for (int r = 0; r < 8; r++) xv[r] = Xs4[(rbase + r) * XS_STRIDE + kc];
        #pragma unroll
        for (int kk = 0; kk < 4; kk++) {
            float4 wv0 = Ws4[(kc * 4 + kk) * DC + c0];
            float4 wv1 = Ws4[(kc * 4 + kk) * DC + c1];
            unsigned long long w0XY = pack2(wv0.x, wv0.y);
            unsigned long long w0ZW = pack2(wv0.z, wv0.w);
            unsigned long long w1XY = pack2(wv1.x, wv1.y);
            unsigned long long w1ZW = pack2(wv1.z, wv1.w);
            #pragma unroll
            for (int r = 0; r < 8; r++) {
                float a = ((const float*)&xv[r])[kk];
                unsigned long long aa = pack2(a, a);
                fma2(acc[r][0], aa, w0XY);
                fma2(acc[r][1], aa, w0ZW);
                fma2(acc[r][2], aa, w1XY);
                fma2(acc[r][3], aa, w1ZW);
            }
        }
    }

    uint4* H4h = (uint4*)g_h;           // one uint4 = 8 halves = chunk pair
    #pragma unroll
    for (int r = 0; r < 8; r++) {
        int gr = row0 + rbase + r;
        if (gr < N_NODES) {
            float s = rsqrtf(g_deg[gr]);
            float4 h0, h1;
            unpack2(acc[r][0], h0.x, h0.y);
            unpack2(acc[r][1], h0.z, h0.w);
            unpack2(acc[r][2], h1.x, h1.y);
            unpack2(acc[r][3], h1.z, h1.w);
            h0.x *= s; h0.y *= s; h0.z *= s; h0.w *= s;
            h1.x *= s; h1.y *= s; h1.z *= s; h1.w *= s;
            __half2 p00 = __floats2half2_rn(h0.x, h0.y);
            __half2 p01 = __floats2half2_rn(h0.z, h0.w);
            __half2 p10 = __floats2half2_rn(h1.x, h1.y);
            __half2 p11 = __floats2half2_rn(h1.z, h1.w);
            uint4 v;
            v.x = *(uint32_t*)&p00; v.y = *(uint32_t*)&p01;
            v.z = *(uint32_t*)&p10; v.w = *(uint32_t*)&p11;
            H4h[(size_t)gr * 12 + tx] = v;
        }
    }
}

// ---------------------------------------------------------------------------
// 6. Gather (atomic-free): one warp per node, lanes 0..23 own one float4 chunk.
//    Metas broadcast-loaded per edge (contiguous in CSR => 1 line/node),
//    4-batch manual unroll for MLP. out = b + h'[n]*dinv + sum h'[row]*nrm.
// ---------------------------------------------------------------------------
__device__ __forceinline__ void acc_edge(float4& acc, uint2 hv, float nrm) {
    float2 f0 = __half22float2(*(__half2*)&hv.x);
    float2 f1 = __half22float2(*(__half2*)&hv.y);
    acc.x += f0.x * nrm; acc.y += f0.y * nrm;
    acc.z += f1.x * nrm; acc.w += f1.y * nrm;
}

__global__ __launch_bounds__(256)
void gather_kernel(const float* __restrict__ b, float* __restrict__ out) {
    int node = (blockIdx.x * blockDim.x + threadIdx.x) >> 5;
    int lane = threadIdx.x & 31;
    if (node >= N_NODES) return;

    int beg = g_off[node];
    int end = g_off[node + 1];
    const uint2* H2 = (const uint2*)g_h;
    bool act = lane < DC;
    float4 acc = make_float4(0.f, 0.f, 0.f, 0.f);

    int j = beg;
    for (; j + 4 <= end; j += 4) {
        int2 m0 = g_srt[j + 0];
        int2 m1 = g_srt[j + 1];
        int2 m2 = g_srt[j + 2];
        int2 m3 = g_srt[j + 3];
        if (act) {
            uint2 v0 = H2[(size_t)m0.x * DC + lane];
            uint2 v1 = H2[(size_t)m1.x * DC + lane];
            uint2 v2 = H2[(size_t)m2.x * DC + lane];
            uint2 v3 = H2[(size_t)m3.x * DC + lane];
            acc_edge(acc, v0, __int_as_float(m0.y));
            acc_edge(acc, v1, __int_as_float(m1.y));
            acc_edge(acc, v2, __int_as_float(m2.y));
            acc_edge(acc, v3, __int_as_float(m3.y));
        }
    }
    for (; j < end; j++) {
        int2 m = g_srt[j];
        if (act) {
            uint2 v = H2[(size_t)m.x * DC + lane];
            acc_edge(acc, v, __int_as_float(m.y));
        }
    }

    if (act) {
        float s = rsqrtf(g_deg[node]);
        uint2 hn = H2[(size_t)node * DC + lane];
        float2 f0 = __half22float2(*(__half2*)&hn.x);
        float2 f1 = __half22float2(*(__half2*)&hn.y);
        float4 bv = ((const float4*)b)[lane];
        float4 o;
        o.x = bv.x + f0.x * s + acc.x;
        o.y = bv.y + f0.y * s + acc.y;
        o.z = bv.z + f1.x * s + acc.z;
        o.w = bv.w + f1.y * s + acc.w;
        ((float4*)out)[(size_t)node * DC + lane] = o;
    }
}

// ---------------------------------------------------------------------------
// Launch.  Inputs: x[N*96] f32, edge_index[2*E] int32/int64, edge_weight[E] f32,
//                  W[96*96] f32, b[96] f32.  Output: [N*96] f32.
// ---------------------------------------------------------------------------
extern "C" void kernel_launch(void* const* d_in, const int* in_sizes, int n_in,
                              void* d_out, int out_size) {
    const float* x = (const float*)d_in[0];
    const void* ei = d_in[1];
    const float* ew = (const float*)d_in[2];
    const float* W = (const float*)d_in[3];
    const float* b = (const float*)d_in[4];
    float* out = (float*)d_out;

    static int smem_set = 0;
    if (!smem_set) {
        cudaFuncSetAttribute(gemm_kernel,
                             cudaFuncAttributeMaxDynamicSharedMemorySize,
                             GEMM_SMEM);
        smem_set = 1;
    }

    init_kernel<<<(N_NODES + 255) / 256, 256>>>((const int*)ei);
    accum_deg_kernel<<<(N_EDGES + 255) / 256, 256>>>(ei, ew);
    scan_kernel<<<1, SCAN_THREADS>>>();
    place_kernel<<<(N_EDGES + 255) / 256, 256>>>(ei, ew);
    gemm_kernel<<<(N_NODES + GEMM_ROWS - 1) / GEMM_ROWS, GEMM_THREADS, GEMM_SMEM>>>(x, W);
    gather_kernel<<<(N_NODES * 32 + 255) / 256, 256>>>(b, out);
}